// round 13
// baseline (speedup 1.0000x reference)
#include <cuda_runtime.h>
#include <cuda_fp16.h>
#include <cstdint>

#define BB 4
#define SS 4096
#define DD 64
#define QT 128
#define KT 128
#define NTH 256
#define NCHUNK (SS / KT)
#define VSTR 72     // fp16 elems per smem row (144B: conflict-free ldmatrix)
#define SSTR 132    // fp32 elems per w-stage row

#define TILE_BYTES (QT * VSTR * 2)
#define BUF_BYTES  (2 * TILE_BYTES)
#define SSTAGE_BYTES (QT * SSTR * 4)                  // 67584
#define SMEM_TOTAL (2 * BUF_BYTES + SSTAGE_BYTES)     // 141312

#define NEGINF __int_as_float(0xff800000)

static __device__ __forceinline__ uint32_t smem_u32(const void* p) {
    uint32_t a;
    asm("{ .reg .u64 t; cvta.to.shared.u64 t, %1; cvt.u32.u64 %0, t; }" : "=r"(a) : "l"(p));
    return a;
}

static __device__ __forceinline__ uint32_t pack_f16(float lo, float hi) {
    uint32_t r;
    asm("cvt.rn.f16x2.f32 %0, %1, %2;" : "=r"(r) : "f"(hi), "f"(lo));
    return r;
}

#define LDSM4(r, a) \
    asm volatile("ldmatrix.sync.aligned.m8n8.x4.shared.b16 {%0,%1,%2,%3}, [%4];" \
                 : "=r"((r)[0]), "=r"((r)[1]), "=r"((r)[2]), "=r"((r)[3]) : "r"(a))

#define LDSM4T(r, a) \
    asm volatile("ldmatrix.sync.aligned.m8n8.x4.trans.shared.b16 {%0,%1,%2,%3}, [%4];" \
                 : "=r"((r)[0]), "=r"((r)[1]), "=r"((r)[2]), "=r"((r)[3]) : "r"(a))

static __device__ __forceinline__ void mma16816(float* d, const uint32_t* a,
                                                uint32_t b0, uint32_t b1) {
    asm volatile(
        "mma.sync.aligned.m16n8k16.row.col.f32.f16.f16.f32 "
        "{%0,%1,%2,%3}, {%4,%5,%6,%7}, {%8,%9}, {%0,%1,%2,%3};"
        : "+f"(d[0]), "+f"(d[1]), "+f"(d[2]), "+f"(d[3])
        : "r"(a[0]), "r"(a[1]), "r"(a[2]), "r"(a[3]), "r"(b0), "r"(b1));
}

// split fp32x4 -> hi/lo fp16x2 pairs into the H/L tiles
static __device__ __forceinline__ void split_store(char* smbase, uint32_t off,
                                                   float4 v) {
    __half hx = __float2half_rn(v.x);
    __half hy = __float2half_rn(v.y);
    __half hz = __float2half_rn(v.z);
    __half hw = __float2half_rn(v.w);
    uint2 H, L;
    H.x = pack_f16(v.x, v.y);
    H.y = pack_f16(v.z, v.w);
    L.x = pack_f16(v.x - __half2float(hx), v.y - __half2float(hy));
    L.y = pack_f16(v.z - __half2float(hz), v.w - __half2float(hw));
    *(uint2*)(smbase + off)              = H;
    *(uint2*)(smbase + off + TILE_BYTES) = L;
}

// Single kernel, two phases:
//   A: GEMM1 + online (m, Z)   (no global score traffic)
//   B: GEMM1 again -> w = exp(s-m)/Z -> write w once -> GEMM2 (P = w) -> ctx
__global__ void __launch_bounds__(NTH, 1)
attn_mma_kernel(const float* __restrict__ Q, const float* __restrict__ V,
                float* __restrict__ ctx_out, float* __restrict__ attn_out)
{
    extern __shared__ __align__(16) char smraw[];   // [buf0 H|L][buf1 H|L][sstage]
    float* sstage = (float*)(smraw + 2 * BUF_BYTES);

    const int tid  = threadIdx.x;
    const int w    = tid >> 5;
    const int lane = tid & 31;
    const int g    = lane >> 2;
    const int p    = lane & 3;
    const int b    = blockIdx.y;
    const int q0   = blockIdx.x * QT;

    const float* Qg = Q + (size_t)(b * SS + q0) * DD;
    const float* Vg = V + (size_t)b * SS * DD;

    const uint32_t sbase = smem_u32(smraw);

    const int ldq  = tid >> 4;
    const int ldd4 = (tid & 15) * 4;
    const uint32_t stoff = (uint32_t)(ldq * VSTR + ldd4) * 2;

    // ---- stage Q -> buf0 hi/lo ----
    #pragma unroll
    for (int r = 0; r < 8; r++) {
        int lin = tid + r * NTH;
        int q  = lin >> 4;
        int d4 = (lin & 15) * 4;
        float4 v = *(const float4*)(Qg + q * DD + d4);
        split_store(smraw, (uint32_t)(q * VSTR + d4) * 2, v);
    }
    __syncthreads();

    const int rA = (lane & 7) + ((lane >> 3) & 1) * 8;
    const int kA = (lane >> 4) * 8;
    const int rB = (lane & 7) + (lane >> 4) * 8;
    const int kB = ((lane >> 3) & 1) * 8;

    uint32_t qh[4][4], ql[4][4];
    #pragma unroll
    for (int ks = 0; ks < 4; ks++) {
        uint32_t off = (uint32_t)((w * 16 + rA) * VSTR + ks * 16 + kA) * 2;
        LDSM4(qh[ks], sbase + off);
        LDSM4(ql[ks], sbase + off + TILE_BYTES);
    }
    __syncthreads();

    float m0 = NEGINF, m1 = NEGINF, z0 = 0.0f, z1 = 0.0f;

    // ================= PHASE A: (m, Z) only =================
    {
        float4 pv[8];
        #pragma unroll
        for (int r = 0; r < 8; r++)
            pv[r] = *(const float4*)(Vg + (size_t)(r * 16 + ldq) * DD + ldd4);

        for (int c = 0; c < NCHUNK; c++) {
            char*    smb = smraw + (c & 1) * BUF_BYTES;
            uint32_t sb  = sbase + (c & 1) * BUF_BYTES;

            #pragma unroll
            for (int r = 0; r < 8; r++)
                split_store(smb, stoff + (uint32_t)(r * 16 * VSTR) * 2, pv[r]);
            __syncthreads();

            if (c + 1 < NCHUNK) {
                const float* vn = Vg + (size_t)((c + 1) * KT + ldq) * DD + ldd4;
                #pragma unroll
                for (int r = 0; r < 8; r++)
                    pv[r] = *(const float4*)(vn + (size_t)(r * 16) * DD);
            }

            float sacc[16][4];
            #pragma unroll
            for (int j = 0; j < 16; j++)
                #pragma unroll
                for (int e = 0; e < 4; e++) sacc[j][e] = 0.0f;

            #pragma unroll
            for (int ks = 0; ks < 4; ks++) {
                #pragma unroll
                for (int np = 0; np < 8; np++) {
                    uint32_t off = (uint32_t)((np * 16 + rB) * VSTR + ks * 16 + kB) * 2;
                    uint32_t bh[4], bl[4];
                    LDSM4(bh, sb + off);
                    LDSM4(bl, sb + off + TILE_BYTES);
                    mma16816(sacc[2 * np],     qh[ks], bh[0], bh[1]);
                    mma16816(sacc[2 * np + 1], qh[ks], bh[2], bh[3]);
                    mma16816(sacc[2 * np],     qh[ks], bl[0], bl[1]);
                    mma16816(sacc[2 * np + 1], qh[ks], bl[2], bl[3]);
                    mma16816(sacc[2 * np],     ql[ks], bh[0], bh[1]);
                    mma16816(sacc[2 * np + 1], ql[ks], bh[2], bh[3]);
                }
            }

            float ml0 = NEGINF, ml1 = NEGINF;
            #pragma unroll
            for (int j = 0; j < 16; j++) {
                ml0 = fmaxf(ml0, fmaxf(sacc[j][0], sacc[j][1]));
                ml1 = fmaxf(ml1, fmaxf(sacc[j][2], sacc[j][3]));
            }
            #pragma unroll
            for (int off = 1; off <= 2; off <<= 1) {
                ml0 = fmaxf(ml0, __shfl_xor_sync(0xffffffffu, ml0, off));
                ml1 = fmaxf(ml1, __shfl_xor_sync(0xffffffffu, ml1, off));
            }
            float mn0 = fmaxf(m0, ml0), mn1 = fmaxf(m1, ml1);
            float sc0 = __expf(m0 - mn0), sc1 = __expf(m1 - mn1);
            m0 = mn0; m1 = mn1;

            float s0 = 0.0f, s1 = 0.0f;
            #pragma unroll
            for (int j = 0; j < 16; j++) {
                s0 += __expf(sacc[j][0] - mn0) + __expf(sacc[j][1] - mn0);
                s1 += __expf(sacc[j][2] - mn1) + __expf(sacc[j][3] - mn1);
            }
            #pragma unroll
            for (int off = 1; off <= 2; off <<= 1) {
                s0 += __shfl_xor_sync(0xffffffffu, s0, off);
                s1 += __shfl_xor_sync(0xffffffffu, s1, off);
            }
            z0 = z0 * sc0 + s0;
            z1 = z1 * sc1 + s1;
            __syncthreads();
        }
    }

    const float iz0 = 1.0f / z0, iz1 = 1.0f / z1;

    float cacc[8][4];
    #pragma unroll
    for (int j = 0; j < 8; j++)
        #pragma unroll
        for (int e = 0; e < 4; e++) cacc[j][e] = 0.0f;

    // ================= PHASE B: w out once + GEMM2 =================
    {
        float4 pv[8];
        #pragma unroll
        for (int r = 0; r < 8; r++)
            pv[r] = *(const float4*)(Vg + (size_t)(r * 16 + ldq) * DD + ldd4);

        for (int c = 0; c < NCHUNK; c++) {
            char*    smb = smraw + (c & 1) * BUF_BYTES;
            uint32_t sb  = sbase + (c & 1) * BUF_BYTES;

            #pragma unroll
            for (int r = 0; r < 8; r++)
                split_store(smb, stoff + (uint32_t)(r * 16 * VSTR) * 2, pv[r]);
            __syncthreads();                               // (1)

            if (c + 1 < NCHUNK) {
                const float* vn = Vg + (size_t)((c + 1) * KT + ldq) * DD + ldd4;
                #pragma unroll
                for (int r = 0; r < 8; r++)
                    pv[r] = *(const float4*)(vn + (size_t)(r * 16) * DD);
            }

            float sacc[16][4];
            #pragma unroll
            for (int j = 0; j < 16; j++)
                #pragma unroll
                for (int e = 0; e < 4; e++) sacc[j][e] = 0.0f;

            #pragma unroll
            for (int ks = 0; ks < 4; ks++) {
                #pragma unroll
                for (int np = 0; np < 8; np++) {
                    uint32_t off = (uint32_t)((np * 16 + rB) * VSTR + ks * 16 + kB) * 2;
                    uint32_t bh[4], bl[4];
                    LDSM4(bh, sb + off);
                    LDSM4(bl, sb + off + TILE_BYTES);
                    mma16816(sacc[2 * np],     qh[ks], bh[0], bh[1]);
                    mma16816(sacc[2 * np + 1], qh[ks], bh[2], bh[3]);
                    mma16816(sacc[2 * np],     qh[ks], bl[0], bl[1]);
                    mma16816(sacc[2 * np + 1], qh[ks], bl[2], bl[3]);
                    mma16816(sacc[2 * np],     ql[ks], bh[0], bh[1]);
                    mma16816(sacc[2 * np + 1], ql[ks], bh[2], bh[3]);
                }
            }

            // ---- w = exp(s - m) * iz  (final weights) ----
            #pragma unroll
            for (int j = 0; j < 16; j++) {
                sacc[j][0] = __expf(sacc[j][0] - m0) * iz0;
                sacc[j][1] = __expf(sacc[j][1] - m0) * iz0;
                sacc[j][2] = __expf(sacc[j][2] - m1) * iz1;
                sacc[j][3] = __expf(sacc[j][3] - m1) * iz1;
            }

            // ---- scatter w to sstage, coalesced STG.128 out (round-11) ----
            {
                float* r0 = sstage + (w * 16 + g) * SSTR;
                float* r1 = r0 + 8 * SSTR;
                #pragma unroll
                for (int np = 0; np < 8; np++) {
                    *(float2*)(r0 + 16 * np + 2 * p)     = make_float2(sacc[2*np][0],   sacc[2*np][1]);
                    *(float2*)(r0 + 16 * np + 8 + 2 * p) = make_float2(sacc[2*np+1][0], sacc[2*np+1][1]);
                    *(float2*)(r1 + 16 * np + 2 * p)     = make_float2(sacc[2*np][2],   sacc[2*np][3]);
                    *(float2*)(r1 + 16 * np + 8 + 2 * p) = make_float2(sacc[2*np+1][2], sacc[2*np+1][3]);
                }
            }
            __syncthreads();                               // (2)
            {
                float* abase = attn_out + (size_t)(b * SS + q0) * SS + c * KT;
                #pragma unroll
                for (int k = 0; k < 16; k++) {
                    int f  = tid + k * NTH;
                    int r  = f >> 5;
                    int cv = f & 31;
                    float4 v = *(const float4*)(sstage + r * SSTR + cv * 4);
                    *(float4*)(abase + (size_t)r * SS + cv * 4) = v;
                }
            }

            // ---- GEMM2: ctx += w(fp16) @ Vh (no rescale; w final) ----
            #pragma unroll
            for (int kk = 0; kk < 8; kk++) {
                uint32_t ah[4];
                ah[0] = pack_f16(sacc[2 * kk][0],     sacc[2 * kk][1]);
                ah[1] = pack_f16(sacc[2 * kk][2],     sacc[2 * kk][3]);
                ah[2] = pack_f16(sacc[2 * kk + 1][0], sacc[2 * kk + 1][1]);
                ah[3] = pack_f16(sacc[2 * kk + 1][2], sacc[2 * kk + 1][3]);
                #pragma unroll
                for (int np = 0; np < 4; np++) {
                    uint32_t off = (uint32_t)((kk * 16 + rA) * VSTR + np * 16 + kA) * 2;
                    uint32_t bh[4];
                    LDSM4T(bh, sb + off);
                    mma16816(cacc[2 * np],     ah, bh[0], bh[1]);
                    mma16816(cacc[2 * np + 1], ah, bh[2], bh[3]);
                }
            }
        }
    }

    // ---- epilogue: cacc IS the context ----
    {
        float* crow0 = ctx_out + (size_t)(b * SS + q0 + w * 16 + g) * DD + 2 * p;
        float* crow1 = crow0 + (size_t)8 * DD;
        #pragma unroll
        for (int j = 0; j < 8; j++) {
            *(float2*)(crow0 + 8 * j) = make_float2(cacc[j][0], cacc[j][1]);
            *(float2*)(crow1 + 8 * j) = make_float2(cacc[j][2], cacc[j][3]);
        }
    }
}

extern "C" void kernel_launch(void* const* d_in, const int* in_sizes, int n_in,
                              void* d_out, int out_size)
{
    const float* Q = (const float*)d_in[0];
    const float* V = (const float*)d_in[1];
    float* out  = (float*)d_out;
    float* ctx  = out;                           // [B, S, D]
    float* attn = out + (size_t)BB * SS * DD;    // [B, S, S]

    cudaFuncSetAttribute(attn_mma_kernel,
                         cudaFuncAttributeMaxDynamicSharedMemorySize, SMEM_TOTAL);

    dim3 grid(SS / QT, BB);   // 32 x 4 = 128 CTAs
    attn_mma_kernel<<<grid, NTH, SMEM_TOTAL>>>(Q, V, ctx, attn);
}

// round 14
// speedup vs baseline: 1.1461x; 1.1461x over previous
#include <cuda_runtime.h>
#include <cuda_fp16.h>
#include <cstdint>

#define BB 4
#define SS 4096
#define DD 64
#define QT 128
#define KT 128
#define NTH 320          // 256 consumer + 64 producer threads
#define NCON 256
#define NCHUNK (SS / KT)
#define VSTR 72          // fp16 elems per smem row (144B: conflict-free ldmatrix)
#define SSTR 132         // fp32 elems per score-stage row

#define TILE_BYTES (QT * VSTR * 2)
#define BUF_BYTES  (2 * TILE_BYTES)
#define SSTAGE_OFF (2 * BUF_BYTES)
#define SSTAGE_BYTES (QT * SSTR * 4)                  // 67584
#define SMEM_TOTAL (SSTAGE_OFF + SSTAGE_BYTES)        // 141312

#define GROWS (BB * SS)

// per-row softmax stats scratch
__device__ float g_rowm[GROWS];
__device__ float g_rowz[GROWS];

#define NEGINF __int_as_float(0xff800000)

// named barriers: 1,2 = fullv[0,1]; 3,4 = emptyv[0,1]; 5 = sfull; 6 = sempty; 7 = consumer-only
#define BARS(id, n) asm volatile("bar.sync %0, %1;" :: "r"(id), "r"(n) : "memory")
#define BARA(id, n) asm volatile("bar.arrive %0, %1;" :: "r"(id), "r"(n) : "memory")

static __device__ __forceinline__ uint32_t smem_u32(const void* p) {
    uint32_t a;
    asm("{ .reg .u64 t; cvta.to.shared.u64 t, %1; cvt.u32.u64 %0, t; }" : "=r"(a) : "l"(p));
    return a;
}

static __device__ __forceinline__ uint32_t pack_f16(float lo, float hi) {
    uint32_t r;
    asm("cvt.rn.f16x2.f32 %0, %1, %2;" : "=r"(r) : "f"(hi), "f"(lo));
    return r;
}

#define LDSM4(r, a) \
    asm volatile("ldmatrix.sync.aligned.m8n8.x4.shared.b16 {%0,%1,%2,%3}, [%4];" \
                 : "=r"((r)[0]), "=r"((r)[1]), "=r"((r)[2]), "=r"((r)[3]) : "r"(a))

#define LDSM4T(r, a) \
    asm volatile("ldmatrix.sync.aligned.m8n8.x4.trans.shared.b16 {%0,%1,%2,%3}, [%4];" \
                 : "=r"((r)[0]), "=r"((r)[1]), "=r"((r)[2]), "=r"((r)[3]) : "r"(a))

static __device__ __forceinline__ void mma16816(float* d, const uint32_t* a,
                                                uint32_t b0, uint32_t b1) {
    asm volatile(
        "mma.sync.aligned.m16n8k16.row.col.f32.f16.f16.f32 "
        "{%0,%1,%2,%3}, {%4,%5,%6,%7}, {%8,%9}, {%0,%1,%2,%3};"
        : "+f"(d[0]), "+f"(d[1]), "+f"(d[2]), "+f"(d[3])
        : "r"(a[0]), "r"(a[1]), "r"(a[2]), "r"(a[3]), "r"(b0), "r"(b1));
}

// split fp32x4 -> hi/lo fp16x2 pairs into the H/L tiles
static __device__ __forceinline__ void split_store(char* smbase, uint32_t off,
                                                   float4 v) {
    __half hx = __float2half_rn(v.x);
    __half hy = __float2half_rn(v.y);
    __half hz = __float2half_rn(v.z);
    __half hw = __float2half_rn(v.w);
    uint2 H, L;
    H.x = pack_f16(v.x, v.y);
    H.y = pack_f16(v.z, v.w);
    L.x = pack_f16(v.x - __half2float(hx), v.y - __half2float(hy));
    L.y = pack_f16(v.z - __half2float(hz), v.w - __half2float(hw));
    *(uint2*)(smbase + off)              = H;
    *(uint2*)(smbase + off + TILE_BYTES) = L;
}

// Warp-specialized kernel: 8 consumer warps (MMA + softmax) + 2 producer
// warps (V staging + score copy-out). Round-11 consumer math unchanged.
__global__ void __launch_bounds__(NTH, 1)
attn_mma_kernel(const float* __restrict__ Q, const float* __restrict__ V,
                float* __restrict__ ctx_out, float* __restrict__ attn_out)
{
    extern __shared__ __align__(16) char smraw[];   // [buf0 H|L][buf1 H|L][sstage]
    float* sstage = (float*)(smraw + SSTAGE_OFF);

    const int tid  = threadIdx.x;
    const int lane = tid & 31;
    const int b    = blockIdx.y;
    const int q0   = blockIdx.x * QT;

    const float* Qg = Q + (size_t)(b * SS + q0) * DD;
    const float* Vg = V + (size_t)b * SS * DD;

    const uint32_t sbase = smem_u32(smraw);

    // ---- stage Q -> sstage area (H at +0, L at +TILE_BYTES), consumers only ----
    if (tid < NCON) {
        #pragma unroll
        for (int r = 0; r < 8; r++) {
            int lin = tid + r * NCON;
            int q  = lin >> 4;
            int d4 = (lin & 15) * 4;
            float4 v = *(const float4*)(Qg + q * DD + d4);
            split_store((char*)smraw + SSTAGE_OFF, (uint32_t)(q * VSTR + d4) * 2, v);
        }
    }
    __syncthreads();   // all 320

    if (tid < NCON) {
        // ================= CONSUMER =================
        const int w = tid >> 5;
        const int g = lane >> 2;
        const int p = lane & 3;

        const int rA = (lane & 7) + ((lane >> 3) & 1) * 8;
        const int kA = (lane >> 4) * 8;
        const int rB = (lane & 7) + (lane >> 4) * 8;
        const int kB = ((lane >> 3) & 1) * 8;

        uint32_t qh[4][4], ql[4][4];
        #pragma unroll
        for (int ks = 0; ks < 4; ks++) {
            uint32_t off = SSTAGE_OFF + (uint32_t)((w * 16 + rA) * VSTR + ks * 16 + kA) * 2;
            LDSM4(qh[ks], sbase + off);
            LDSM4(ql[ks], sbase + off + TILE_BYTES);
        }
        BARS(7, NCON);   // all consumers extracted Q frags before any scatter

        float m0 = NEGINF, m1 = NEGINF, z0 = 0.0f, z1 = 0.0f;
        float cacc[8][4];
        #pragma unroll
        for (int j = 0; j < 8; j++)
            #pragma unroll
            for (int e = 0; e < 4; e++) cacc[j][e] = 0.0f;

        for (int c = 0; c < NCHUNK; c++) {
            uint32_t sb = sbase + (c & 1) * BUF_BYTES;
            BARS(1 + (c & 1), NTH);                    // V(c) staged

            // ---- GEMM1: 3-combo fp16 split ----
            float sacc[16][4];
            #pragma unroll
            for (int j = 0; j < 16; j++)
                #pragma unroll
                for (int e = 0; e < 4; e++) sacc[j][e] = 0.0f;

            #pragma unroll
            for (int ks = 0; ks < 4; ks++) {
                #pragma unroll
                for (int np = 0; np < 8; np++) {
                    uint32_t off = (uint32_t)((np * 16 + rB) * VSTR + ks * 16 + kB) * 2;
                    uint32_t bh[4], bl[4];
                    LDSM4(bh, sb + off);
                    LDSM4(bl, sb + off + TILE_BYTES);
                    mma16816(sacc[2 * np],     qh[ks], bh[0], bh[1]);
                    mma16816(sacc[2 * np + 1], qh[ks], bh[2], bh[3]);
                    mma16816(sacc[2 * np],     qh[ks], bl[0], bl[1]);
                    mma16816(sacc[2 * np + 1], qh[ks], bl[2], bl[3]);
                    mma16816(sacc[2 * np],     ql[ks], bh[0], bh[1]);
                    mma16816(sacc[2 * np + 1], ql[ks], bh[2], bh[3]);
                }
            }

            // ---- scatter raw scores to sstage (producers copy them out) ----
            if (c > 0) BARS(6, NTH);                   // sstage drained
            {
                float* r0 = sstage + (w * 16 + g) * SSTR;
                float* r1 = r0 + 8 * SSTR;
                #pragma unroll
                for (int np = 0; np < 8; np++) {
                    *(float2*)(r0 + 16 * np + 2 * p)     = make_float2(sacc[2*np][0],   sacc[2*np][1]);
                    *(float2*)(r0 + 16 * np + 8 + 2 * p) = make_float2(sacc[2*np+1][0], sacc[2*np+1][1]);
                    *(float2*)(r1 + 16 * np + 2 * p)     = make_float2(sacc[2*np][2],   sacc[2*np][3]);
                    *(float2*)(r1 + 16 * np + 8 + 2 * p) = make_float2(sacc[2*np+1][2], sacc[2*np+1][3]);
                }
            }
            BARA(5, NTH);                              // sfull

            // ---- softmax (overlaps producer copy-out) ----
            float ml0 = NEGINF, ml1 = NEGINF;
            #pragma unroll
            for (int j = 0; j < 16; j++) {
                ml0 = fmaxf(ml0, fmaxf(sacc[j][0], sacc[j][1]));
                ml1 = fmaxf(ml1, fmaxf(sacc[j][2], sacc[j][3]));
            }
            #pragma unroll
            for (int off = 1; off <= 2; off <<= 1) {
                ml0 = fmaxf(ml0, __shfl_xor_sync(0xffffffffu, ml0, off));
                ml1 = fmaxf(ml1, __shfl_xor_sync(0xffffffffu, ml1, off));
            }
            float mn0 = fmaxf(m0, ml0), mn1 = fmaxf(m1, ml1);
            float sc0 = __expf(m0 - mn0), sc1 = __expf(m1 - mn1);
            m0 = mn0; m1 = mn1;

            float s0 = 0.0f, s1 = 0.0f;
            #pragma unroll
            for (int j = 0; j < 16; j++) {
                sacc[j][0] = __expf(sacc[j][0] - mn0);
                sacc[j][1] = __expf(sacc[j][1] - mn0);
                sacc[j][2] = __expf(sacc[j][2] - mn1);
                sacc[j][3] = __expf(sacc[j][3] - mn1);
                s0 += sacc[j][0] + sacc[j][1];
                s1 += sacc[j][2] + sacc[j][3];
            }
            #pragma unroll
            for (int off = 1; off <= 2; off <<= 1) {
                s0 += __shfl_xor_sync(0xffffffffu, s0, off);
                s1 += __shfl_xor_sync(0xffffffffu, s1, off);
            }
            z0 = z0 * sc0 + s0;
            z1 = z1 * sc1 + s1;

            #pragma unroll
            for (int j = 0; j < 8; j++) {
                cacc[j][0] *= sc0; cacc[j][1] *= sc0;
                cacc[j][2] *= sc1; cacc[j][3] *= sc1;
            }

            // ---- GEMM2: ctx += P(fp16) @ Vh ----
            #pragma unroll
            for (int kk = 0; kk < 8; kk++) {
                uint32_t ah[4];
                ah[0] = pack_f16(sacc[2 * kk][0],     sacc[2 * kk][1]);
                ah[1] = pack_f16(sacc[2 * kk][2],     sacc[2 * kk][3]);
                ah[2] = pack_f16(sacc[2 * kk + 1][0], sacc[2 * kk + 1][1]);
                ah[3] = pack_f16(sacc[2 * kk + 1][2], sacc[2 * kk + 1][3]);
                #pragma unroll
                for (int np = 0; np < 4; np++) {
                    uint32_t off = (uint32_t)((kk * 16 + rA) * VSTR + np * 16 + kA) * 2;
                    uint32_t bh[4];
                    LDSM4T(bh, sb + off);
                    mma16816(cacc[2 * np],     ah, bh[0], bh[1]);
                    mma16816(cacc[2 * np + 1], ah, bh[2], bh[3]);
                }
            }
            BARA(3 + (c & 1), NTH);                    // emptyv: buf free
        }

        // ---- epilogue ----
        const float iz0 = 1.0f / z0, iz1 = 1.0f / z1;
        {
            float* crow0 = ctx_out + (size_t)(b * SS + q0 + w * 16 + g) * DD + 2 * p;
            float* crow1 = crow0 + (size_t)8 * DD;
            #pragma unroll
            for (int j = 0; j < 8; j++) {
                *(float2*)(crow0 + 8 * j) = make_float2(cacc[j][0] * iz0, cacc[j][1] * iz0);
                *(float2*)(crow1 + 8 * j) = make_float2(cacc[j][2] * iz1, cacc[j][3] * iz1);
            }
        }
        if (p == 0) {
            int row = b * SS + q0 + w * 16 + g;
            g_rowm[row]     = m0;
            g_rowz[row]     = z0;
            g_rowm[row + 8] = m1;
            g_rowz[row + 8] = z1;
        }
    } else {
        // ================= PRODUCER (warps 8-9) =================
        const int pt = tid - NCON;   // 0..63

        // stage V(0) into buf0
        {
            char* smb = smraw;
            #pragma unroll
            for (int batch = 0; batch < 2; batch++) {
                float4 vv[16];
                #pragma unroll
                for (int r = 0; r < 16; r++) {
                    int lin = pt + (batch * 16 + r) * 64;
                    vv[r] = *(const float4*)(Vg + (size_t)(lin >> 4) * DD + (lin & 15) * 4);
                }
                #pragma unroll
                for (int r = 0; r < 16; r++) {
                    int lin = pt + (batch * 16 + r) * 64;
                    split_store(smb, (uint32_t)((lin >> 4) * VSTR + (lin & 15) * 4) * 2, vv[r]);
                }
            }
            BARA(1, NTH);   // fullv[0]
        }

        for (int c = 0; c < NCHUNK; c++) {
            if (c + 1 < NCHUNK) {
                int i = (c + 1) & 1;
                if (c + 1 >= 2) BARS(3 + i, NTH);      // emptyv[i]
                char* smb = smraw + i * BUF_BYTES;
                const float* vsrc = Vg + (size_t)((c + 1) * KT) * DD;
                #pragma unroll
                for (int batch = 0; batch < 2; batch++) {
                    float4 vv[16];
                    #pragma unroll
                    for (int r = 0; r < 16; r++) {
                        int lin = pt + (batch * 16 + r) * 64;
                        vv[r] = *(const float4*)(vsrc + (size_t)(lin >> 4) * DD + (lin & 15) * 4);
                    }
                    #pragma unroll
                    for (int r = 0; r < 16; r++) {
                        int lin = pt + (batch * 16 + r) * 64;
                        split_store(smb, (uint32_t)((lin >> 4) * VSTR + (lin & 15) * 4) * 2, vv[r]);
                    }
                }
                BARA(1 + i, NTH);                      // fullv[i]
            }

            BARS(5, NTH);                              // sfull: scores staged
            {
                float* abase = attn_out + (size_t)(b * SS + q0) * SS + c * KT;
                #pragma unroll 8
                for (int k = 0; k < 64; k++) {
                    int f  = pt + k * 64;
                    int r  = f >> 5;
                    int cv = f & 31;
                    float4 v = *(const float4*)(sstage + r * SSTR + cv * 4);
                    *(float4*)(abase + (size_t)r * SS + cv * 4) = v;
                }
            }
            BARA(6, NTH);                              // sempty
        }
    }
}

// Norm kernel: w = exp(s - m)/Z in place. High columns first (L2-resident),
// allocating loads, streaming stores.
__global__ void __launch_bounds__(512)
attn_norm_kernel(float* __restrict__ attn)
{
    const int row = blockIdx.x;
    const float m = g_rowm[row];
    const float r = 1.0f / g_rowz[row];
    float4* base = (float4*)(attn + (size_t)row * SS) + threadIdx.x;
    #pragma unroll
    for (int k = 1; k >= 0; k--) {
        float4 v = base[k * 512];
        v.x = __expf(v.x - m) * r;
        v.y = __expf(v.y - m) * r;
        v.z = __expf(v.z - m) * r;
        v.w = __expf(v.w - m) * r;
        __stcs(base + k * 512, v);
    }
}

extern "C" void kernel_launch(void* const* d_in, const int* in_sizes, int n_in,
                              void* d_out, int out_size)
{
    const float* Q = (const float*)d_in[0];
    const float* V = (const float*)d_in[1];
    float* out  = (float*)d_out;
    float* ctx  = out;                           // [B, S, D]
    float* attn = out + (size_t)BB * SS * DD;    // [B, S, S]

    cudaFuncSetAttribute(attn_mma_kernel,
                         cudaFuncAttributeMaxDynamicSharedMemorySize, SMEM_TOTAL);

    dim3 grid(SS / QT, BB);   // 32 x 4 = 128 CTAs
    attn_mma_kernel<<<grid, NTH, SMEM_TOTAL>>>(Q, V, ctx, attn);

    attn_norm_kernel<<<GROWS, 512>>>(attn);
}

// round 15
// speedup vs baseline: 1.2007x; 1.0476x over previous
#include <cuda_runtime.h>
#include <cuda_fp16.h>
#include <cstdint>

#define BB 4
#define SS 4096
#define DD 64
#define QT 128
#define KT 128
#define NTH 320          // 256 consumer + 64 producer threads
#define NCON 256
#define NCHUNK (SS / KT)
#define VSTR 72          // fp16 elems per smem row (144B: conflict-free ldmatrix)

#define TILE_BYTES (QT * VSTR * 2)
#define BUF_BYTES  (2 * TILE_BYTES)
#define QSTAGE_OFF (2 * BUF_BYTES)
#define SMEM_TOTAL (QSTAGE_OFF + BUF_BYTES)   // V double buffer + Q staging

#define GROWS (BB * SS)

// per-row softmax stats scratch
__device__ float g_rowm[GROWS];
__device__ float g_rowz[GROWS];

#define NEGINF __int_as_float(0xff800000)

// named barriers: 1,2 = fullA[0,1]; 3,4 = fullB[0,1]; 5,6 = empty[0,1]
#define BARS(id, n) asm volatile("bar.sync %0, %1;" :: "r"(id), "r"(n) : "memory")
#define BARA(id, n) asm volatile("bar.arrive %0, %1;" :: "r"(id), "r"(n) : "memory")

static __device__ __forceinline__ uint32_t smem_u32(const void* p) {
    uint32_t a;
    asm("{ .reg .u64 t; cvta.to.shared.u64 t, %1; cvt.u32.u64 %0, t; }" : "=r"(a) : "l"(p));
    return a;
}

static __device__ __forceinline__ uint32_t pack_f16(float lo, float hi) {
    uint32_t r;
    asm("cvt.rn.f16x2.f32 %0, %1, %2;" : "=r"(r) : "f"(hi), "f"(lo));
    return r;
}

#define LDSM4(r, a) \
    asm volatile("ldmatrix.sync.aligned.m8n8.x4.shared.b16 {%0,%1,%2,%3}, [%4];" \
                 : "=r"((r)[0]), "=r"((r)[1]), "=r"((r)[2]), "=r"((r)[3]) : "r"(a))

#define LDSM4T(r, a) \
    asm volatile("ldmatrix.sync.aligned.m8n8.x4.trans.shared.b16 {%0,%1,%2,%3}, [%4];" \
                 : "=r"((r)[0]), "=r"((r)[1]), "=r"((r)[2]), "=r"((r)[3]) : "r"(a))

static __device__ __forceinline__ void mma16816(float* d, const uint32_t* a,
                                                uint32_t b0, uint32_t b1) {
    asm volatile(
        "mma.sync.aligned.m16n8k16.row.col.f32.f16.f16.f32 "
        "{%0,%1,%2,%3}, {%4,%5,%6,%7}, {%8,%9}, {%0,%1,%2,%3};"
        : "+f"(d[0]), "+f"(d[1]), "+f"(d[2]), "+f"(d[3])
        : "r"(a[0]), "r"(a[1]), "r"(a[2]), "r"(a[3]), "r"(b0), "r"(b1));
}

// split fp32x4 -> hi/lo fp16x2 pairs into the H/L tiles
static __device__ __forceinline__ void split_store(char* smbase, uint32_t off,
                                                   float4 v) {
    __half hx = __float2half_rn(v.x);
    __half hy = __float2half_rn(v.y);
    __half hz = __float2half_rn(v.z);
    __half hw = __float2half_rn(v.w);
    uint2 H, L;
    H.x = pack_f16(v.x, v.y);
    H.y = pack_f16(v.z, v.w);
    L.x = pack_f16(v.x - __half2float(hx), v.y - __half2float(hy));
    L.y = pack_f16(v.z - __half2float(hz), v.w - __half2float(hw));
    *(uint2*)(smbase + off)              = H;
    *(uint2*)(smbase + off + TILE_BYTES) = L;
}

// Ping-pong kernel: 2 free-running consumer groups (4 warps each) + 2
// producer warps staging V. Group B seeded one staging period behind A.
__global__ void __launch_bounds__(NTH, 1)
attn_mma_kernel(const float* __restrict__ Q, const float* __restrict__ V,
                float* __restrict__ ctx_out, float* __restrict__ attn_out)
{
    extern __shared__ __align__(16) char smraw[];   // [buf0 H|L][buf1 H|L][Qstage H|L]

    const int tid  = threadIdx.x;
    const int lane = tid & 31;
    const int b    = blockIdx.y;
    const int q0   = blockIdx.x * QT;

    const float* Qg = Q + (size_t)(b * SS + q0) * DD;
    const float* Vg = V + (size_t)b * SS * DD;

    const uint32_t sbase = smem_u32(smraw);

    // ---- stage Q -> Qstage area (consumers only) ----
    if (tid < NCON) {
        #pragma unroll
        for (int r = 0; r < 8; r++) {
            int lin = tid + r * NCON;
            int q  = lin >> 4;
            int d4 = (lin & 15) * 4;
            float4 v = *(const float4*)(Qg + q * DD + d4);
            split_store((char*)smraw + QSTAGE_OFF, (uint32_t)(q * VSTR + d4) * 2, v);
        }
    }
    __syncthreads();   // all 320

    if (tid < NCON) {
        // ================= CONSUMER (two free-running groups) =================
        const int w  = tid >> 5;
        const int ga = (w < 4);               // group A: warps 0-3 (rows 0-63)
        const int g  = lane >> 2;
        const int p  = lane & 3;
        const int fid0 = ga ? 1 : 3;          // full barrier base id

        const int rA = (lane & 7) + ((lane >> 3) & 1) * 8;
        const int kA = (lane >> 4) * 8;
        const int rB = (lane & 7) + (lane >> 4) * 8;
        const int kB = ((lane >> 3) & 1) * 8;

        uint32_t qh[4][4], ql[4][4];
        #pragma unroll
        for (int ks = 0; ks < 4; ks++) {
            uint32_t off = QSTAGE_OFF + (uint32_t)((w * 16 + rA) * VSTR + ks * 16 + kA) * 2;
            LDSM4(qh[ks], sbase + off);
            LDSM4(ql[ks], sbase + off + TILE_BYTES);
        }

        float m0 = NEGINF, m1 = NEGINF, z0 = 0.0f, z1 = 0.0f;
        float cacc[8][4];
        #pragma unroll
        for (int j = 0; j < 8; j++)
            #pragma unroll
            for (int e = 0; e < 4; e++) cacc[j][e] = 0.0f;

        for (int c = 0; c < NCHUNK; c++) {
            uint32_t sb = sbase + (c & 1) * BUF_BYTES;
            BARS(fid0 + (c & 1), 192);                 // this group's V(c) ready

            // ---- GEMM1: 3-combo fp16 split ----
            float sacc[16][4];
            #pragma unroll
            for (int j = 0; j < 16; j++)
                #pragma unroll
                for (int e = 0; e < 4; e++) sacc[j][e] = 0.0f;

            #pragma unroll
            for (int ks = 0; ks < 4; ks++) {
                #pragma unroll
                for (int np = 0; np < 8; np++) {
                    uint32_t off = (uint32_t)((np * 16 + rB) * VSTR + ks * 16 + kB) * 2;
                    uint32_t bh[4], bl[4];
                    LDSM4(bh, sb + off);
                    LDSM4(bl, sb + off + TILE_BYTES);
                    mma16816(sacc[2 * np],     qh[ks], bh[0], bh[1]);
                    mma16816(sacc[2 * np + 1], qh[ks], bh[2], bh[3]);
                    mma16816(sacc[2 * np],     qh[ks], bl[0], bl[1]);
                    mma16816(sacc[2 * np + 1], qh[ks], bl[2], bl[3]);
                    mma16816(sacc[2 * np],     ql[ks], bh[0], bh[1]);
                    mma16816(sacc[2 * np + 1], ql[ks], bh[2], bh[3]);
                }
            }

            // ---- raw scores out (direct, round-5 style) ----
            {
                float* srow0 = attn_out + (size_t)(b * SS + q0 + w * 16 + g) * SS + c * KT + 2 * p;
                float* srow1 = srow0 + (size_t)8 * SS;
                #pragma unroll
                for (int j = 0; j < 16; j++) {
                    *(float2*)(srow0 + 8 * j) = make_float2(sacc[j][0], sacc[j][1]);
                    *(float2*)(srow1 + 8 * j) = make_float2(sacc[j][2], sacc[j][3]);
                }
            }

            // ---- online softmax ----
            float ml0 = NEGINF, ml1 = NEGINF;
            #pragma unroll
            for (int j = 0; j < 16; j++) {
                ml0 = fmaxf(ml0, fmaxf(sacc[j][0], sacc[j][1]));
                ml1 = fmaxf(ml1, fmaxf(sacc[j][2], sacc[j][3]));
            }
            #pragma unroll
            for (int off = 1; off <= 2; off <<= 1) {
                ml0 = fmaxf(ml0, __shfl_xor_sync(0xffffffffu, ml0, off));
                ml1 = fmaxf(ml1, __shfl_xor_sync(0xffffffffu, ml1, off));
            }
            float mn0 = fmaxf(m0, ml0), mn1 = fmaxf(m1, ml1);
            float sc0 = __expf(m0 - mn0), sc1 = __expf(m1 - mn1);
            m0 = mn0; m1 = mn1;

            float s0 = 0.0f, s1 = 0.0f;
            #pragma unroll
            for (int j = 0; j < 16; j++) {
                sacc[j][0] = __expf(sacc[j][0] - mn0);
                sacc[j][1] = __expf(sacc[j][1] - mn0);
                sacc[j][2] = __expf(sacc[j][2] - mn1);
                sacc[j][3] = __expf(sacc[j][3] - mn1);
                s0 += sacc[j][0] + sacc[j][1];
                s1 += sacc[j][2] + sacc[j][3];
            }
            #pragma unroll
            for (int off = 1; off <= 2; off <<= 1) {
                s0 += __shfl_xor_sync(0xffffffffu, s0, off);
                s1 += __shfl_xor_sync(0xffffffffu, s1, off);
            }
            z0 = z0 * sc0 + s0;
            z1 = z1 * sc1 + s1;

            #pragma unroll
            for (int j = 0; j < 8; j++) {
                cacc[j][0] *= sc0; cacc[j][1] *= sc0;
                cacc[j][2] *= sc1; cacc[j][3] *= sc1;
            }

            // ---- GEMM2: ctx += P(fp16) @ Vh ----
            #pragma unroll
            for (int kk = 0; kk < 8; kk++) {
                uint32_t ah[4];
                ah[0] = pack_f16(sacc[2 * kk][0],     sacc[2 * kk][1]);
                ah[1] = pack_f16(sacc[2 * kk][2],     sacc[2 * kk][3]);
                ah[2] = pack_f16(sacc[2 * kk + 1][0], sacc[2 * kk + 1][1]);
                ah[3] = pack_f16(sacc[2 * kk + 1][2], sacc[2 * kk + 1][3]);
                #pragma unroll
                for (int np = 0; np < 4; np++) {
                    uint32_t off = (uint32_t)((kk * 16 + rA) * VSTR + np * 16 + kA) * 2;
                    uint32_t bh[4];
                    LDSM4T(bh, sb + off);
                    mma16816(cacc[2 * np],     ah, bh[0], bh[1]);
                    mma16816(cacc[2 * np + 1], ah, bh[2], bh[3]);
                }
            }
            BARA(5 + (c & 1), NTH);                    // this group done with buf
        }

        // ---- epilogue ----
        const float iz0 = 1.0f / z0, iz1 = 1.0f / z1;
        {
            float* crow0 = ctx_out + (size_t)(b * SS + q0 + w * 16 + g) * DD + 2 * p;
            float* crow1 = crow0 + (size_t)8 * DD;
            #pragma unroll
            for (int j = 0; j < 8; j++) {
                *(float2*)(crow0 + 8 * j) = make_float2(cacc[j][0] * iz0, cacc[j][1] * iz0);
                *(float2*)(crow1 + 8 * j) = make_float2(cacc[j][2] * iz1, cacc[j][3] * iz1);
            }
        }
        if (p == 0) {
            int row = b * SS + q0 + w * 16 + g;
            g_rowm[row]     = m0;
            g_rowz[row]     = z0;
            g_rowm[row + 8] = m1;
            g_rowz[row + 8] = z1;
        }
    } else {
        // ================= PRODUCER (warps 8-9): V staging only =================
        const int pt = tid - NCON;   // 0..63

        auto stage = [&](int c) {
            char* smb = smraw + (c & 1) * BUF_BYTES;
            const float* vsrc = Vg + (size_t)(c * KT) * DD;
            #pragma unroll
            for (int batch = 0; batch < 2; batch++) {
                float4 vv[16];
                #pragma unroll
                for (int r = 0; r < 16; r++) {
                    int lin = pt + (batch * 16 + r) * 64;
                    vv[r] = *(const float4*)(vsrc + (size_t)(lin >> 4) * DD + (lin & 15) * 4);
                }
                #pragma unroll
                for (int r = 0; r < 16; r++) {
                    int lin = pt + (batch * 16 + r) * 64;
                    split_store(smb, (uint32_t)((lin >> 4) * VSTR + (lin & 15) * 4) * 2, vv[r]);
                }
            }
        };

        stage(0);
        BARA(1, 192);             // fullA[0] — group A starts
        stage(1);
        BARA(3, 192);             // fullB[0] — group B released late (seed offset)
        BARA(2, 192);             // fullA[1]
        BARA(4, 192);             // fullB[1]

        for (int c = 2; c < NCHUNK; c++) {
            BARS(5 + (c & 1), NTH);          // both groups done with buf (c-2)
            stage(c);
            BARA(1 + (c & 1), 192);          // fullA[c&1]
            BARA(3 + (c & 1), 192);          // fullB[c&1]
        }
    }
}

// Norm kernel: w = exp(s - m)/Z in place. High columns first (L2-resident),
// allocating loads, streaming stores.
__global__ void __launch_bounds__(512)
attn_norm_kernel(float* __restrict__ attn)
{
    const int row = blockIdx.x;
    const float m = g_rowm[row];
    const float r = 1.0f / g_rowz[row];
    float4* base = (float4*)(attn + (size_t)row * SS) + threadIdx.x;
    #pragma unroll
    for (int k = 1; k >= 0; k--) {
        float4 v = base[k * 512];
        v.x = __expf(v.x - m) * r;
        v.y = __expf(v.y - m) * r;
        v.z = __expf(v.z - m) * r;
        v.w = __expf(v.w - m) * r;
        __stcs(base + k * 512, v);
    }
}

extern "C" void kernel_launch(void* const* d_in, const int* in_sizes, int n_in,
                              void* d_out, int out_size)
{
    const float* Q = (const float*)d_in[0];
    const float* V = (const float*)d_in[1];
    float* out  = (float*)d_out;
    float* ctx  = out;                           // [B, S, D]
    float* attn = out + (size_t)BB * SS * DD;    // [B, S, S]

    cudaFuncSetAttribute(attn_mma_kernel,
                         cudaFuncAttributeMaxDynamicSharedMemorySize, SMEM_TOTAL);

    dim3 grid(SS / QT, BB);   // 32 x 4 = 128 CTAs
    attn_mma_kernel<<<grid, NTH, SMEM_TOTAL>>>(Q, V, ctx, attn);

    attn_norm_kernel<<<GROWS, 512>>>(attn);
}